// round 2
// baseline (speedup 1.0000x reference)
#include <cuda_runtime.h>
#include <cuda_bf16.h>
#include <cstdint>

// Loss_Labels: -mean over B of ( label==1 ? log_softmax(s,a)[0]
//                              : label==2 ? log_softmax(s,a)[1] : 0 )
//
// NOTE: reference runs under default JAX config (x64 disabled), so the
// "int64" labels materialize as int32 on device. 12 B/element streamed,
// B = 8.4M -> ~100 MB. HBM-bound; target ~16-25 us on GB300.

#define NB 2048
#define NT 256

__device__ float g_partials[NB];

__device__ __forceinline__ float err_term(float s, float a, int lab) {
    // d = a - s; lse - s = max(d,0) + log1p(exp(-|d|))
    float d   = a - s;
    float lp0 = -(fmaxf(d, 0.0f) + log1pf(expf(-fabsf(d))));  // log p(syn)
    float lp1 = d + lp0;                                       // log p(ant)
    return (lab == 1) ? lp0 : ((lab == 2) ? lp1 : 0.0f);
}

__global__ void __launch_bounds__(NT)
loss_reduce_kernel(const float4* __restrict__ s4,
                   const float4* __restrict__ a4,
                   const int4*   __restrict__ l4,
                   int nvec)
{
    float acc = 0.0f;
    const int stride = gridDim.x * blockDim.x;
    for (int i = blockIdx.x * blockDim.x + threadIdx.x; i < nvec; i += stride) {
        float4 s = s4[i];
        float4 a = a4[i];
        int4   l = l4[i];
        acc += err_term(s.x, a.x, l.x);
        acc += err_term(s.y, a.y, l.y);
        acc += err_term(s.z, a.z, l.z);
        acc += err_term(s.w, a.w, l.w);
    }

    // deterministic block tree reduction
    __shared__ float sm[NT];
    sm[threadIdx.x] = acc;
    __syncthreads();
#pragma unroll
    for (int off = NT / 2; off > 0; off >>= 1) {
        if (threadIdx.x < off) sm[threadIdx.x] += sm[threadIdx.x + off];
        __syncthreads();
    }
    if (threadIdx.x == 0) g_partials[blockIdx.x] = sm[0];
}

__global__ void __launch_bounds__(NT)
loss_final_kernel(const float* __restrict__ s,
                  const float* __restrict__ a,
                  const int*   __restrict__ lab,
                  float* __restrict__ out,
                  int n, int nvec)
{
    // sum the block partials (deterministic fixed-order tree)
    float acc = 0.0f;
    for (int i = threadIdx.x; i < NB; i += NT) acc += g_partials[i];

    // scalar tail for n % 4 != 0 (n = 8388608 is divisible; kept for safety)
    for (int i = nvec * 4 + threadIdx.x; i < n; i += NT)
        acc += err_term(s[i], a[i], lab[i]);

    __shared__ float sm[NT];
    sm[threadIdx.x] = acc;
    __syncthreads();
#pragma unroll
    for (int off = NT / 2; off > 0; off >>= 1) {
        if (threadIdx.x < off) sm[threadIdx.x] += sm[threadIdx.x + off];
        __syncthreads();
    }
    if (threadIdx.x == 0) out[0] = -sm[0] / (float)n;
}

extern "C" void kernel_launch(void* const* d_in, const int* in_sizes, int n_in,
                              void* d_out, int out_size)
{
    const float* s   = (const float*)d_in[0];  // synonymy_score [B]
    const float* a   = (const float*)d_in[1];  // antonymy_score [B]
    const int*   lab = (const int*)d_in[2];    // labels [B] (int32 on device)
    float*       out = (float*)d_out;

    const int n    = in_sizes[0];
    const int nvec = n / 4;

    loss_reduce_kernel<<<NB, NT>>>((const float4*)s, (const float4*)a,
                                   (const int4*)lab, nvec);
    loss_final_kernel<<<1, NT>>>(s, a, lab, out, n, nvec);
}